// round 1
// baseline (speedup 1.0000x reference)
#include <cuda_runtime.h>

#define T_TOK 8192
#define HDIM  1024
#define NEXP  8

#define BM 128
#define BN 128
#define BK 8
#define TM 8
#define TN 8

// ---------------- scratch (device globals; no allocation allowed) ----------
__device__ int   g_counts[NEXP];
__device__ int   g_offsets[NEXP + 1];
__device__ int   g_cursor[NEXP];
__device__ int   g_expert[T_TOK];
__device__ float g_gate[T_TOK];
__device__ int   g_perm[T_TOK];

// ---------------- phase 0: reset ----------------
__global__ void reset_kernel() {
    if (threadIdx.x < NEXP) g_counts[threadIdx.x] = 0;
}

// ---------------- phase 1: router (1 warp per token) ----------------
__global__ void router_kernel(const float* __restrict__ x,
                              const float* __restrict__ rw,
                              const float* __restrict__ rb) {
    int gwarp = (blockIdx.x * blockDim.x + threadIdx.x) >> 5;
    int lane  = threadIdx.x & 31;
    if (gwarp >= T_TOK) return;

    const float* xr = x + (size_t)gwarp * HDIM;
    float acc[NEXP];
#pragma unroll
    for (int e = 0; e < NEXP; e++) acc[e] = 0.f;

    // 1024 elems / (32 lanes * 4) = 8 iterations of float4
#pragma unroll
    for (int i = 0; i < HDIM / 128; i++) {
        int h = (i * 32 + lane) * 4;
        float4 xv = *reinterpret_cast<const float4*>(xr + h);
        float xa[4] = {xv.x, xv.y, xv.z, xv.w};
#pragma unroll
        for (int c = 0; c < 4; c++) {
            const float4 w0 = __ldg(reinterpret_cast<const float4*>(rw + (size_t)(h + c) * NEXP));
            const float4 w1 = __ldg(reinterpret_cast<const float4*>(rw + (size_t)(h + c) * NEXP + 4));
            float xc = xa[c];
            acc[0] += xc * w0.x; acc[1] += xc * w0.y;
            acc[2] += xc * w0.z; acc[3] += xc * w0.w;
            acc[4] += xc * w1.x; acc[5] += xc * w1.y;
            acc[6] += xc * w1.z; acc[7] += xc * w1.w;
        }
    }

    // warp reduction
#pragma unroll
    for (int e = 0; e < NEXP; e++) {
#pragma unroll
        for (int off = 16; off > 0; off >>= 1)
            acc[e] += __shfl_xor_sync(0xffffffffu, acc[e], off);
    }

    if (lane == 0) {
        float logit[NEXP];
        float best = -1e30f;
        int   bi = 0;
#pragma unroll
        for (int e = 0; e < NEXP; e++) {
            logit[e] = acc[e] + rb[e];
            if (logit[e] > best) { best = logit[e]; bi = e; }  // first-max wins (jnp.argmax)
        }
        float s = 0.f;
#pragma unroll
        for (int e = 0; e < NEXP; e++) s += expf(logit[e] - best);
        g_expert[gwarp] = bi;
        g_gate[gwarp]   = 1.0f / s;     // softmax prob of the argmax
        atomicAdd(&g_counts[bi], 1);
    }
}

// ---------------- phase 2: exclusive scan over 8 experts ----------------
__global__ void scan_kernel() {
    if (threadIdx.x == 0) {
        int o = 0;
#pragma unroll
        for (int e = 0; e < NEXP; e++) {
            g_offsets[e] = o;
            g_cursor[e]  = o;
            o += g_counts[e];
        }
        g_offsets[NEXP] = o;
    }
}

// ---------------- phase 3: build permutation ----------------
__global__ void assign_kernel() {
    int t = blockIdx.x * blockDim.x + threadIdx.x;
    if (t < T_TOK) {
        int e = g_expert[t];
        int slot = atomicAdd(&g_cursor[e], 1);
        g_perm[slot] = t;
    }
}

// ---------------- phase 4: grouped SGEMM ----------------
// grid: (HDIM/BN, T_TOK/BM, NEXP), block: 256 threads
// out[t, n] = gate[t] * ( sum_k x[t,k] * W[e,k,n] + b[e,n] )
__global__ __launch_bounds__(256, 2)
void moe_gemm_kernel(const float* __restrict__ x,
                     const float* __restrict__ ew,
                     const float* __restrict__ eb,
                     float* __restrict__ out) {
    const int e     = blockIdx.z;
    const int start = g_offsets[e];
    const int end   = g_offsets[e + 1];
    const int m0    = start + blockIdx.y * BM;
    if (m0 >= end) return;
    const int rows = min(BM, end - m0);
    const int n0   = blockIdx.x * BN;

    __shared__ float As[BK][BM];
    __shared__ float Bs[BK][BN];
    __shared__ int   sTok[BM];
    __shared__ float sGate[BM];

    const int tid = threadIdx.x;

    if (tid < BM) {
        if (tid < rows) {
            int t = g_perm[m0 + tid];
            sTok[tid]  = t;
            sGate[tid] = g_gate[t];
        } else {
            sTok[tid]  = -1;
            sGate[tid] = 0.f;
        }
    }
    __syncthreads();

    const float* W = ew + (size_t)e * HDIM * HDIM;

    // A-tile load mapping: 256 threads -> 128 rows x 2 float4
    const int a_row = tid >> 1;
    const int a_col = (tid & 1) * 4;
    // B-tile load mapping: 8 rows x 32 float4
    const int b_row = tid >> 5;
    const int b_col = (tid & 31) * 4;

    // compute mapping: split 4+4 so LDS.128 addresses are conflict-free
    const int tx = tid & 15;   // N direction
    const int ty = tid >> 4;   // M direction

    const int tokA = sTok[a_row];
    const float* xrow = (tokA >= 0) ? (x + (size_t)tokA * HDIM) : nullptr;

    float acc[TM][TN];
#pragma unroll
    for (int i = 0; i < TM; i++)
#pragma unroll
        for (int j = 0; j < TN; j++) acc[i][j] = 0.f;

    for (int k0 = 0; k0 < HDIM; k0 += BK) {
        float4 av = make_float4(0.f, 0.f, 0.f, 0.f);
        if (xrow) av = *reinterpret_cast<const float4*>(xrow + k0 + a_col);
        As[a_col + 0][a_row] = av.x;
        As[a_col + 1][a_row] = av.y;
        As[a_col + 2][a_row] = av.z;
        As[a_col + 3][a_row] = av.w;

        float4 bv = *reinterpret_cast<const float4*>(W + (size_t)(k0 + b_row) * HDIM + n0 + b_col);
        *reinterpret_cast<float4*>(&Bs[b_row][b_col]) = bv;

        __syncthreads();

#pragma unroll
        for (int kk = 0; kk < BK; kk++) {
            float ra[TM], rb4[TN];
            *reinterpret_cast<float4*>(&ra[0])  = *reinterpret_cast<const float4*>(&As[kk][ty * 4]);
            *reinterpret_cast<float4*>(&ra[4])  = *reinterpret_cast<const float4*>(&As[kk][64 + ty * 4]);
            *reinterpret_cast<float4*>(&rb4[0]) = *reinterpret_cast<const float4*>(&Bs[kk][tx * 4]);
            *reinterpret_cast<float4*>(&rb4[4]) = *reinterpret_cast<const float4*>(&Bs[kk][64 + tx * 4]);
#pragma unroll
            for (int i = 0; i < TM; i++)
#pragma unroll
                for (int j = 0; j < TN; j++)
                    acc[i][j] += ra[i] * rb4[j];
        }
        __syncthreads();
    }

    // epilogue: out = gate * (acc + bias)
    const float* brow = eb + (size_t)e * HDIM + n0;
#pragma unroll
    for (int i = 0; i < TM; i++) {
        int r = (i < 4) ? (ty * 4 + i) : (64 + ty * 4 + (i - 4));
        if (r >= rows) continue;
        int   t = sTok[r];
        float g = sGate[r];
        float* orow = out + (size_t)t * HDIM + n0;
#pragma unroll
        for (int jh = 0; jh < 2; jh++) {
            int n = (jh == 0) ? (tx * 4) : (64 + tx * 4);
            int jb = jh * 4;
            float4 bb = *reinterpret_cast<const float4*>(brow + n);
            float4 v;
            v.x = g * (acc[i][jb + 0] + bb.x);
            v.y = g * (acc[i][jb + 1] + bb.y);
            v.z = g * (acc[i][jb + 2] + bb.z);
            v.w = g * (acc[i][jb + 3] + bb.w);
            *reinterpret_cast<float4*>(orow + n) = v;
        }
    }
}

// ---------------- launch ----------------
extern "C" void kernel_launch(void* const* d_in, const int* in_sizes, int n_in,
                              void* d_out, int out_size) {
    const float* x  = (const float*)d_in[0];   // [4,2048,1024]
    const float* rw = (const float*)d_in[1];   // [1024,8]
    const float* rb = (const float*)d_in[2];   // [8]
    const float* ew = (const float*)d_in[3];   // [8,1024,1024]
    const float* eb = (const float*)d_in[4];   // [8,1024]
    float* out = (float*)d_out;                // [4,2048,1024]

    reset_kernel<<<1, 32>>>();
    router_kernel<<<T_TOK / 8, 256>>>(x, rw, rb);   // 8 warps/block, 1 token/warp
    scan_kernel<<<1, 32>>>();
    assign_kernel<<<T_TOK / 256, 256>>>();

    dim3 grid(HDIM / BN, T_TOK / BM, NEXP);
    moe_gemm_kernel<<<grid, 256>>>(x, ew, eb, out);
}

// round 3
// speedup vs baseline: 1.9551x; 1.9551x over previous
#include <cuda_runtime.h>
#include <cuda_bf16.h>
#include <cstdint>

#define T_TOK 8192
#define HDIM  1024
#define NEXP  8
#define TPAD  (T_TOK + NEXP*128)

#define BM 128
#define BN 128
#define BK 64
#define NITER 48        // 3072 / 64

// ---------------- device scratch ----------------
__device__ int   g_counts[NEXP];
__device__ int   g_offpad[NEXP + 1];
__device__ int   g_cursor[NEXP];
__device__ int   g_expert[T_TOK];
__device__ float g_gate[T_TOK];
__device__ int   g_slot[T_TOK];
__device__ int   g_tokpad[TPAD];
__device__ __nv_bfloat16 g_xhi[(size_t)TPAD * HDIM];
__device__ __nv_bfloat16 g_xlo[(size_t)TPAD * HDIM];
__device__ __nv_bfloat16 g_whi[(size_t)NEXP * HDIM * HDIM];  // [e][n][k]
__device__ __nv_bfloat16 g_wlo[(size_t)NEXP * HDIM * HDIM];

// ---------------- helpers ----------------
__device__ __forceinline__ uint32_t smem_u32(const void* p) {
    uint32_t a;
    asm("{ .reg .u64 t; cvta.to.shared.u64 t, %1; cvt.u32.u64 %0, t; }" : "=r"(a) : "l"(p));
    return a;
}
__device__ __forceinline__ void cp16(uint32_t dst, const void* src) {
    asm volatile("cp.async.cg.shared.global [%0], [%1], 16;" :: "r"(dst), "l"(src));
}
__device__ __forceinline__ void cp_commit() {
    asm volatile("cp.async.commit_group;" ::: "memory");
}
template <int N>
__device__ __forceinline__ void cp_wait() {
    asm volatile("cp.async.wait_group %0;" :: "n"(N) : "memory");
}
#define LDSM4(R, addr) \
    asm volatile("ldmatrix.sync.aligned.m8n8.x4.shared.b16 {%0,%1,%2,%3}, [%4];" \
                 : "=r"((R)[0]), "=r"((R)[1]), "=r"((R)[2]), "=r"((R)[3]) : "r"(addr))
#define MMA16816(D, A, B0, B1) \
    asm volatile("mma.sync.aligned.m16n8k16.row.col.f32.bf16.bf16.f32 " \
                 "{%0,%1,%2,%3}, {%4,%5,%6,%7}, {%8,%9}, {%0,%1,%2,%3};" \
                 : "+f"((D)[0]), "+f"((D)[1]), "+f"((D)[2]), "+f"((D)[3]) \
                 : "r"((A)[0]), "r"((A)[1]), "r"((A)[2]), "r"((A)[3]), "r"(B0), "r"(B1))

// ---------------- phase 0: reset ----------------
__global__ void reset_kernel() {
    if (threadIdx.x < NEXP) g_counts[threadIdx.x] = 0;
}

// ---------------- phase 1: router ----------------
__global__ void router_kernel(const float* __restrict__ x,
                              const float* __restrict__ rw,
                              const float* __restrict__ rb) {
    int gwarp = (blockIdx.x * blockDim.x + threadIdx.x) >> 5;
    int lane  = threadIdx.x & 31;
    if (gwarp >= T_TOK) return;

    const float* xr = x + (size_t)gwarp * HDIM;
    float acc[NEXP];
#pragma unroll
    for (int e = 0; e < NEXP; e++) acc[e] = 0.f;

#pragma unroll
    for (int i = 0; i < HDIM / 128; i++) {
        int h = (i * 32 + lane) * 4;
        float4 xv = *reinterpret_cast<const float4*>(xr + h);
        float xa[4] = {xv.x, xv.y, xv.z, xv.w};
#pragma unroll
        for (int c = 0; c < 4; c++) {
            const float4 w0 = __ldg(reinterpret_cast<const float4*>(rw + (size_t)(h + c) * NEXP));
            const float4 w1 = __ldg(reinterpret_cast<const float4*>(rw + (size_t)(h + c) * NEXP + 4));
            float xc = xa[c];
            acc[0] += xc * w0.x; acc[1] += xc * w0.y;
            acc[2] += xc * w0.z; acc[3] += xc * w0.w;
            acc[4] += xc * w1.x; acc[5] += xc * w1.y;
            acc[6] += xc * w1.z; acc[7] += xc * w1.w;
        }
    }
#pragma unroll
    for (int e = 0; e < NEXP; e++) {
#pragma unroll
        for (int off = 16; off > 0; off >>= 1)
            acc[e] += __shfl_xor_sync(0xffffffffu, acc[e], off);
    }
    if (lane == 0) {
        float logit[NEXP];
        float best = -1e30f;
        int   bi = 0;
#pragma unroll
        for (int e = 0; e < NEXP; e++) {
            logit[e] = acc[e] + rb[e];
            if (logit[e] > best) { best = logit[e]; bi = e; }
        }
        float s = 0.f;
#pragma unroll
        for (int e = 0; e < NEXP; e++) s += expf(logit[e] - best);
        g_expert[gwarp] = bi;
        g_gate[gwarp]   = 1.0f / s;
        atomicAdd(&g_counts[bi], 1);
    }
}

// ---------------- phase 2: scan ----------------
__global__ void scan_kernel() {
    if (threadIdx.x == 0) {
        int o = 0;
#pragma unroll
        for (int e = 0; e < NEXP; e++) {
            g_offpad[e] = o;
            g_cursor[e] = o;
            o += ((g_counts[e] + 127) >> 7) << 7;
        }
        g_offpad[NEXP] = o;
    }
}

// ---------------- phase 3: permutation ----------------
__global__ void assign_kernel() {
    int t = blockIdx.x * blockDim.x + threadIdx.x;
    if (t < T_TOK) {
        int e = g_expert[t];
        int slot = atomicAdd(&g_cursor[e], 1);
        g_tokpad[slot] = t;
        g_slot[t] = slot;
    }
}

// ---------------- phase 4: permute + split x ----------------
__global__ void split_x_kernel(const float* __restrict__ x) {
    int t    = (blockIdx.x * blockDim.x + threadIdx.x) >> 5;
    int lane = threadIdx.x & 31;
    if (t >= T_TOK) return;
    int slot = g_slot[t];
    const float* xr = x + (size_t)t * HDIM;
    __nv_bfloat16* hi = g_xhi + (size_t)slot * HDIM;
    __nv_bfloat16* lo = g_xlo + (size_t)slot * HDIM;
#pragma unroll
    for (int i = 0; i < 4; i++) {
        int base = (i * 32 + lane) * 8;
        float4 a = *reinterpret_cast<const float4*>(xr + base);
        float4 b = *reinterpret_cast<const float4*>(xr + base + 4);
        float va[8] = {a.x, a.y, a.z, a.w, b.x, b.y, b.z, b.w};
        uint32_t hw[4], lw[4];
#pragma unroll
        for (int q = 0; q < 4; q++) {
            __nv_bfloat16 h0 = __float2bfloat16_rn(va[2*q]);
            __nv_bfloat16 h1 = __float2bfloat16_rn(va[2*q+1]);
            __nv_bfloat16 l0 = __float2bfloat16_rn(va[2*q]   - __bfloat162float(h0));
            __nv_bfloat16 l1 = __float2bfloat16_rn(va[2*q+1] - __bfloat162float(h1));
            hw[q] = (uint32_t)__bfloat16_as_ushort(h0) | ((uint32_t)__bfloat16_as_ushort(h1) << 16);
            lw[q] = (uint32_t)__bfloat16_as_ushort(l0) | ((uint32_t)__bfloat16_as_ushort(l1) << 16);
        }
        *reinterpret_cast<uint4*>(hi + base) = make_uint4(hw[0], hw[1], hw[2], hw[3]);
        *reinterpret_cast<uint4*>(lo + base) = make_uint4(lw[0], lw[1], lw[2], lw[3]);
    }
}

// ---------------- phase 5: transpose + split W ----------------
__global__ void split_w_kernel(const float* __restrict__ ew) {
    __shared__ float tile[32][33];
    int e  = blockIdx.z;
    int k0 = blockIdx.y * 32, n0 = blockIdx.x * 32;
    int tx = threadIdx.x, ty = threadIdx.y;   // 32 x 8
    const float* W = ew + (size_t)e * HDIM * HDIM;
#pragma unroll
    for (int i = 0; i < 4; i++)
        tile[ty + i * 8][tx] = W[(size_t)(k0 + ty + i * 8) * HDIM + n0 + tx];
    __syncthreads();
#pragma unroll
    for (int i = 0; i < 4; i++) {
        int n = n0 + ty + i * 8, k = k0 + tx;
        float v = tile[tx][ty + i * 8];
        __nv_bfloat16 h = __float2bfloat16_rn(v);
        __nv_bfloat16 l = __float2bfloat16_rn(v - __bfloat162float(h));
        size_t idx = (size_t)e * HDIM * HDIM + (size_t)n * HDIM + k;
        g_whi[idx] = h;
        g_wlo[idx] = l;
    }
}

// ---------------- phase 6: grouped bf16 HMMA GEMM ----------------
// SMEM: As 2x16KB @0, Bs 2x16KB @32768, tok @65536, gate @66048
static constexpr uint32_t OFF_B    = 32768;
static constexpr uint32_t OFF_TOK  = 65536;
static constexpr uint32_t OFF_GATE = 66048;
static constexpr uint32_t SMEM_TOTAL = 66560;

__device__ __forceinline__ void issue_stage(int j, int tid, int m0, int n0,
                                            size_t ebase, uint32_t sbase) {
    int seg = j >> 4;                 // 0,1,2
    int kin = (j & 15) * BK;
    const __nv_bfloat16* Ab = (seg == 2) ? g_xlo : g_xhi;
    const __nv_bfloat16* Bb = ((seg == 1) ? g_wlo : g_whi) + ebase;
    uint32_t as = sbase + (uint32_t)(j & 1) * 16384;
    uint32_t bs = sbase + OFF_B + (uint32_t)(j & 1) * 16384;
#pragma unroll
    for (int i = 0; i < 4; i++) {           // A: 128 rows x 8 chunks
        int op = tid + i * 256;
        int r = op >> 3, c = op & 7;
        cp16(as + r * 128 + ((c * 16) ^ ((r & 7) << 4)),
             Ab + (size_t)(m0 + r) * HDIM + kin + c * 8);
    }
#pragma unroll
    for (int i = 0; i < 4; i++) {           // B: 128 rows x 8 chunks
        int op = tid + i * 256;
        int r = op >> 3, c = op & 7;
        cp16(bs + r * 128 + ((c * 16) ^ ((r & 7) << 4)),
             Bb + (size_t)(n0 + r) * HDIM + kin + c * 8);
    }
    cp_commit();
}

__global__ __launch_bounds__(256, 2)
void moe_gemm_kernel(const float* __restrict__ eb, float* __restrict__ out) {
    extern __shared__ __align__(1024) char smem[];
    const int m0 = blockIdx.y * BM;
    if (m0 >= g_offpad[NEXP]) return;
    int e = 0;
    while (m0 >= g_offpad[e + 1]) e++;
    const int rows_valid = min(BM, g_offpad[e] + g_counts[e] - m0);
    const int n0 = blockIdx.x * BN;
    const int tid = threadIdx.x;
    const uint32_t sbase = smem_u32(smem);
    const size_t ebase = (size_t)e * HDIM * HDIM;

    if (tid < 128) {
        int tok = g_tokpad[m0 + tid] & (T_TOK - 1);
        ((int*)(smem + OFF_TOK))[tid] = tok;
        ((float*)(smem + OFF_GATE))[tid] = g_gate[tok];
    }

    issue_stage(0, tid, m0, n0, ebase, sbase);
    issue_stage(1, tid, m0, n0, ebase, sbase);

    const int lane = tid & 31, wid = tid >> 5;
    const int warp_m = (wid >> 1) * 32;
    const int warp_n = (wid & 1) * 64;
    const int idx = lane & 7, grp = lane >> 3;

    // ldmatrix per-thread geometry
    const int arow = warp_m + (grp & 1) * 8 + idx;         // + mt*16
    const uint32_t axor = (uint32_t)((arow & 7) << 4);
    const uint32_t acsel = (uint32_t)((grp >> 1) * 16);
    const int brow = warp_n + (grp >> 1) * 8 + idx;        // + bt*16
    const uint32_t bxor = (uint32_t)((brow & 7) << 4);
    const uint32_t bcsel = (uint32_t)((grp & 1) * 16);

    float acc[2][8][4];
#pragma unroll
    for (int i = 0; i < 2; i++)
#pragma unroll
        for (int j = 0; j < 8; j++)
#pragma unroll
            for (int q = 0; q < 4; q++) acc[i][j][q] = 0.f;

    for (int k = 0; k < NITER; k++) {
        cp_wait<1>();
        __syncthreads();
        uint32_t as = sbase + (uint32_t)(k & 1) * 16384;
        uint32_t bs = sbase + OFF_B + (uint32_t)(k & 1) * 16384;
#pragma unroll
        for (int step = 0; step < 4; step++) {
            uint32_t kc = (uint32_t)(step * 32);
            uint32_t a[2][4], b[4][4];
#pragma unroll
            for (int mt = 0; mt < 2; mt++)
                LDSM4(a[mt], as + (uint32_t)(arow + mt * 16) * 128 + ((kc + acsel) ^ axor));
#pragma unroll
            for (int bt = 0; bt < 4; bt++)
                LDSM4(b[bt], bs + (uint32_t)(brow + bt * 16) * 128 + ((kc + bcsel) ^ bxor));
#pragma unroll
            for (int mt = 0; mt < 2; mt++)
#pragma unroll
                for (int bt = 0; bt < 4; bt++) {
                    MMA16816(acc[mt][2 * bt],     a[mt], b[bt][0], b[bt][1]);
                    MMA16816(acc[mt][2 * bt + 1], a[mt], b[bt][2], b[bt][3]);
                }
        }
        __syncthreads();
        if (k + 2 < NITER) issue_stage(k + 2, tid, m0, n0, ebase, sbase);
        else cp_commit();
    }

    // epilogue
    const int* sTok = (const int*)(smem + OFF_TOK);
    const float* sGate = (const float*)(smem + OFF_GATE);
    const float* ebias = eb + (size_t)e * HDIM + n0;
    const int colq = (lane & 3) * 2;
#pragma unroll
    for (int mt = 0; mt < 2; mt++) {
        int r_lo = warp_m + mt * 16 + (lane >> 2);
        int r_hi = r_lo + 8;
        bool v_lo = r_lo < rows_valid, v_hi = r_hi < rows_valid;
        int   t_lo = sTok[r_lo],  t_hi = sTok[r_hi];
        float g_lo = sGate[r_lo], g_hi = sGate[r_hi];
        float* o_lo = out + (size_t)t_lo * HDIM + n0;
        float* o_hi = out + (size_t)t_hi * HDIM + n0;
#pragma unroll
        for (int nt = 0; nt < 8; nt++) {
            int col = warp_n + nt * 8 + colq;
            float2 bv = *reinterpret_cast<const float2*>(ebias + col);
            if (v_lo) {
                float2 v;
                v.x = g_lo * (acc[mt][nt][0] + bv.x);
                v.y = g_lo * (acc[mt][nt][1] + bv.y);
                *reinterpret_cast<float2*>(o_lo + col) = v;
            }
            if (v_hi) {
                float2 v;
                v.x = g_hi * (acc[mt][nt][2] + bv.x);
                v.y = g_hi * (acc[mt][nt][3] + bv.y);
                *reinterpret_cast<float2*>(o_hi + col) = v;
            }
        }
    }
}

// ---------------- launch ----------------
extern "C" void kernel_launch(void* const* d_in, const int* in_sizes, int n_in,
                              void* d_out, int out_size) {
    const float* x  = (const float*)d_in[0];
    const float* rw = (const float*)d_in[1];
    const float* rb = (const float*)d_in[2];
    const float* ew = (const float*)d_in[3];
    const float* eb = (const float*)d_in[4];
    float* out = (float*)d_out;

    cudaFuncSetAttribute(moe_gemm_kernel,
                         cudaFuncAttributeMaxDynamicSharedMemorySize, SMEM_TOTAL);

    reset_kernel<<<1, 32>>>();
    router_kernel<<<T_TOK / 8, 256>>>(x, rw, rb);
    scan_kernel<<<1, 32>>>();
    assign_kernel<<<T_TOK / 256, 256>>>();
    split_x_kernel<<<T_TOK / 8, 256>>>(x);
    split_w_kernel<<<dim3(32, 32, 8), dim3(32, 8)>>>(ew);
    moe_gemm_kernel<<<dim3(HDIM / BN, TPAD / BM), 256, SMEM_TOTAL>>>(eb, out);
}